// round 8
// baseline (speedup 1.0000x reference)
#include <cuda_runtime.h>
#include <cstdint>

#define N_MAX 25000
#define E_MAX 400000
#define CCH 64
#define TILE 128
#define ETHREADS 1024
#define EGRID 148

static __device__ float4 d_x[N_MAX * CCH];   // up-projected  [N][C][4]
static __device__ float4 d_M[N_MAX * CCH];   // scatter accum [N][C][4]
static __device__ float  d_ef[E_MAX * 8];    // edge bessel feats
static __device__ float4 d_Y[E_MAX];         // sqrt3 * unit vec (w unused)
static __device__ float  d_U[4 * CCH];       // embW @ lin_up_W0[0]
static __device__ float  d_W0c[CCH * CCH];   // prod_lin_W0[0] @ lin_up_W0[1]
static __device__ float  d_W1c[CCH * CCH];   // prod_lin_W1[0] @ lin_up_W1[1]

__device__ __forceinline__ float silu_f(float v) {
    return v / (1.0f + __expf(-v));
}
__device__ __forceinline__ unsigned long long pack2(float x) {
    unsigned long long r;
    asm("mov.b64 %0, {%1, %1};" : "=l"(r) : "f"(x));
    return r;
}
__device__ __forceinline__ void fma2(unsigned long long &d, unsigned long long a, unsigned long long b) {
    asm("fma.rn.f32x2 %0, %1, %2, %0;" : "+l"(d) : "l"(a), "l"(b));
}
__device__ __forceinline__ float2 unpack2(unsigned long long v) {
    float2 r;
    asm("mov.b64 {%0, %1}, %2;" : "=f"(r.x), "=f"(r.y) : "l"(v));
    return r;
}

// ---------------------------------------------------------------------------
// Per-edge geometry (accurate sinf — MUFU __sinf is NOT accurate at 8pi)
// ---------------------------------------------------------------------------
__global__ void k_geom(const float* __restrict__ pos, const int* __restrict__ ei, int E_) {
    int e = blockIdx.x * blockDim.x + threadIdx.x;
    if (e >= E_) return;
    int s = ei[e];
    int r_ = ei[E_ + e];
    float vx = pos[3*s + 0] - pos[3*r_ + 0];
    float vy = pos[3*s + 1] - pos[3*r_ + 1];
    float vz = pos[3*s + 2] - pos[3*r_ + 2];
    float rr = sqrtf(vx*vx + vy*vy + vz*vz);
    rr = fmaxf(rr, 1e-6f);
    float inv_r = 1.0f / rr;
    const float SQRT3 = 1.7320508075688772f;
    float4 Y;
    Y.x = SQRT3 * vx * inv_r;
    Y.y = SQRT3 * vy * inv_r;
    Y.z = SQRT3 * vz * inv_r;
    Y.w = 0.0f;
    d_Y[e] = Y;
    float x = rr * 0.2f;
    float x2 = x * x;
    float x6 = x2 * x2 * x2;
    float fc = 1.0f - 28.0f*x6 + 48.0f*x6*x - 21.0f*x6*x2;
    fc = (x < 1.0f) ? fc : 0.0f;
    const float BC = 0.6324555320336759f;      // sqrt(2/5)
    const float PI_O_R = 0.6283185307179586f;  // pi/5
    float pref = BC * inv_r * fc;
    float ef[8];
    #pragma unroll
    for (int k = 0; k < 8; k++)
        ef[k] = pref * sinf((float)(k + 1) * PI_O_R * rr);
    float4* dst = (float4*)(d_ef + (size_t)e * 8);
    dst[0] = make_float4(ef[0], ef[1], ef[2], ef[3]);
    dst[1] = make_float4(ef[4], ef[5], ef[6], ef[7]);
}

// ---------------------------------------------------------------------------
// Weight prep (single block)
// ---------------------------------------------------------------------------
__global__ void __launch_bounds__(256) k_prepw(
    const float* __restrict__ embW, const float* __restrict__ LU0_l0,
    const float* __restrict__ PL0_l0, const float* __restrict__ LU0_l1,
    const float* __restrict__ PL1_l0, const float* __restrict__ LU1_l1)
{
    int tid = threadIdx.x;
    {
        int s = tid >> 6, j = tid & 63;
        float acc = 0.0f;
        for (int k = 0; k < 64; k++) acc += embW[s * 64 + k] * LU0_l0[k * 64 + j];
        d_U[tid] = acc;
    }
    for (int t = tid; t < 4096; t += 256) {
        int i = t >> 6, j = t & 63;
        float a0 = 0.0f, a1 = 0.0f;
        for (int k = 0; k < 64; k++) {
            a0 += PL0_l0[i * 64 + k] * LU0_l1[k * 64 + j];
            a1 += PL1_l0[i * 64 + k] * LU1_l1[k * 64 + j];
        }
        d_W0c[t] = a0;
        d_W1c[t] = a1;
    }
}

// ---------------------------------------------------------------------------
// Layer-0 seed: x = row-select of U (h1 == 0), zero M
// ---------------------------------------------------------------------------
__global__ void k_seed(const int* __restrict__ species, int N_) {
    int idx = blockIdx.x * blockDim.x + threadIdx.x;
    if (idx >= N_ * CCH) return;
    int n = idx >> 6, c = idx & 63;
    int sp = species[n];
    d_x[idx] = make_float4(d_U[sp * CCH + c], 0.0f, 0.0f, 0.0f);
    d_M[idx] = make_float4(0, 0, 0, 0);
}

// ---------------------------------------------------------------------------
// Persistent fused edge kernel, 128-edge tiles.
//   Warp = 4 edges x 64 cols everywhere: a-operands broadcast (LDS.128
//   batched over K), b-operands 256B-contiguous LDS.64, accumulators in
//   registers (max 40), E fused into D's epilogue (coalesced gather+red.v4).
// ---------------------------------------------------------------------------
#define HSTR 68
#define SME_W1   0
#define SME_W2   512
#define SME_W3   4608
#define SME_HA   25088
#define SME_HB   33792
#define SME_EF   42496
#define SME_Y    43520
#define SME_SND  44032
#define SME_RCV  44160
#define SME_TOT  44288   // floats (~173 KB)

template<bool FIRST>
__device__ __forceinline__ void emit_msg(float* dst, float4 xs, float4 Yv,
                                         float t0, float t1, float t2,
                                         float t3, float t4) {
    const float INV_SQRT3 = 0.5773502691896258f;
    const float INV_SQRT2 = 0.7071067811865475f;
    float m0, m1x, m1y, m1z;
    if (FIRST) {
        m0 = t0 * xs.x;
        float a = t1 * xs.x;
        m1x = a * Yv.x;
        m1y = a * Yv.y;
        m1z = a * Yv.z;
    } else {
        float dotv = xs.y * Yv.x + xs.z * Yv.y + xs.w * Yv.z;
        m0 = t0 * xs.x + t3 * dotv * INV_SQRT3;
        float cx = xs.z * Yv.z - xs.w * Yv.y;
        float cy = xs.w * Yv.x - xs.y * Yv.z;
        float cz = xs.y * Yv.y - xs.z * Yv.x;
        float a = t1 * xs.x;
        float t4s = t4 * INV_SQRT2;
        m1x = a * Yv.x + t2 * xs.y + t4s * cx;
        m1y = a * Yv.y + t2 * xs.z + t4s * cy;
        m1z = a * Yv.z + t2 * xs.w + t4s * cz;
    }
    asm volatile("red.global.add.v4.f32 [%0], {%1,%2,%3,%4};"
                 :: "l"(dst), "f"(m0), "f"(m1x), "f"(m1y), "f"(m1z)
                 : "memory");
}

template<bool FIRST>
__global__ void __launch_bounds__(ETHREADS, 1) k_edge(
    const int* __restrict__ ei,
    const float* __restrict__ W1g, const float* __restrict__ W2g,
    const float* __restrict__ W3g, int E_)
{
    extern __shared__ float sm[];
    float* sW1 = sm + SME_W1;
    float* sW2 = sm + SME_W2;
    float* sW3 = sm + SME_W3;
    float* sHa = sm + SME_HA;    // [128][68]
    float* sHb = sm + SME_HB;    // [128][68]
    float* sEF = sm + SME_EF;
    float4* sY = (float4*)(sm + SME_Y);
    int* sSend = (int*)(sm + SME_SND);
    int* sRecv = (int*)(sm + SME_RCV);
    const int tid = threadIdx.x;
    const int lane = tid & 31;
    const int w = tid >> 5;

    // one-time weight load (persistent block)
    for (int i = tid; i < 512; i += ETHREADS) sW1[i] = W1g[i];
    for (int i = tid; i < 4096; i += ETHREADS) sW2[i] = W2g[i];
    for (int i = tid; i < 20480; i += ETHREADS) sW3[i] = W3g[i];

    int nTiles = (E_ + TILE - 1) / TILE;
    for (int t = blockIdx.x; t < nTiles; t += gridDim.x) {
        long long base = (long long)t * TILE;
        __syncthreads();   // weights ready (iter 0) / prev tile done
        if (tid < 256) {
            long long e = base + (tid >> 1);
            float4 v = make_float4(0, 0, 0, 0);
            if (e < E_) v = ((const float4*)d_ef)[e * 2 + (tid & 1)];
            ((float4*)sEF)[tid] = v;
        } else if (tid < 384) {
            int i = tid - 256;
            long long e = base + i;
            float4 y = make_float4(0, 0, 0, 0);
            if (e < E_) y = d_Y[e];
            sY[i] = y;
        } else if (tid < 512) {
            int i = tid - 384;
            long long e = base + i;
            int s = 0, r = -1;
            if (e < E_) { s = ei[e]; r = ei[E_ + e]; }
            sSend[i] = s;
            sRecv[i] = r;
        }
        __syncthreads();

        // Phase B: H1 = silu(EF @ W1).  thread: 1 edge x 8 cols.
        {
            int e = tid >> 3;
            int j0 = (tid & 7) << 3;
            const float4* efp = (const float4*)&sEF[e * 8];
            float4 efa = efp[0], efb = efp[1];
            float ef[8] = {efa.x, efa.y, efa.z, efa.w, efb.x, efb.y, efb.z, efb.w};
            unsigned long long acc[4] = {};
            #pragma unroll
            for (int k = 0; k < 8; k++) {
                unsigned long long a2 = pack2(ef[k]);
                ulonglong2 b01 = *(const ulonglong2*)&sW1[k * 64 + j0];
                ulonglong2 b23 = *(const ulonglong2*)&sW1[k * 64 + j0 + 4];
                fma2(acc[0], a2, b01.x);
                fma2(acc[1], a2, b01.y);
                fma2(acc[2], a2, b23.x);
                fma2(acc[3], a2, b23.y);
            }
            float out[8];
            #pragma unroll
            for (int i = 0; i < 4; i++) {
                float2 p = unpack2(acc[i]);
                out[2 * i] = silu_f(p.x);
                out[2 * i + 1] = silu_f(p.y);
            }
            float* ha = &sHa[e * HSTR + j0];
            *(float4*)ha = make_float4(out[0], out[1], out[2], out[3]);
            *(float4*)(ha + 4) = make_float4(out[4], out[5], out[6], out[7]);
        }
        __syncthreads();

        // Phase C: H2 = silu(H1 @ W2).  warp: 4 edges x 64 cols;
        // thread: 4 edges x 1 colpair.  a broadcast, K batched by 4.
        {
            int e0 = w * 4;
            int cb = lane * 2;
            unsigned long long acc[4] = {};
            #pragma unroll 2
            for (int cc = 0; cc < 64; cc += 4) {
                float a0[4], a1[4], a2v[4], a3[4];
                *(float4*)a0  = *(const float4*)&sHa[(e0 + 0) * HSTR + cc];
                *(float4*)a1  = *(const float4*)&sHa[(e0 + 1) * HSTR + cc];
                *(float4*)a2v = *(const float4*)&sHa[(e0 + 2) * HSTR + cc];
                *(float4*)a3  = *(const float4*)&sHa[(e0 + 3) * HSTR + cc];
                #pragma unroll
                for (int k = 0; k < 4; k++) {
                    unsigned long long b = *(const unsigned long long*)&sW2[(cc + k) * 64 + cb];
                    fma2(acc[0], pack2(a0[k]), b);
                    fma2(acc[1], pack2(a1[k]), b);
                    fma2(acc[2], pack2(a2v[k]), b);
                    fma2(acc[3], pack2(a3[k]), b);
                }
            }
            #pragma unroll
            for (int i = 0; i < 4; i++) {
                float2 p = unpack2(acc[i]);
                float* hb = &sHb[(e0 + i) * HSTR + cb];
                hb[0] = silu_f(p.x);
                hb[1] = silu_f(p.y);
            }
        }
        __syncthreads();

        // Phase D+E: TPW = H2 @ W3, tensor product, coalesced red scatter.
        // warp: 4 edges x 64 cols x NB paths; thread: 4 edges x 1 colpair.
        {
            int e0 = w * 4;
            int cb = lane * 2;
            if (FIRST) {
                unsigned long long acc[4][2];
                #pragma unroll
                for (int i = 0; i < 4; i++) { acc[i][0] = 0ull; acc[i][1] = 0ull; }
                #pragma unroll 2
                for (int cc = 0; cc < 64; cc += 4) {
                    float a0[4], a1[4], a2v[4], a3[4];
                    *(float4*)a0  = *(const float4*)&sHb[(e0 + 0) * HSTR + cc];
                    *(float4*)a1  = *(const float4*)&sHb[(e0 + 1) * HSTR + cc];
                    *(float4*)a2v = *(const float4*)&sHb[(e0 + 2) * HSTR + cc];
                    *(float4*)a3  = *(const float4*)&sHb[(e0 + 3) * HSTR + cc];
                    #pragma unroll
                    for (int k = 0; k < 4; k++) {
                        unsigned long long b0 = *(const unsigned long long*)&sW3[(cc + k) * 320 + cb];
                        unsigned long long b1 = *(const unsigned long long*)&sW3[(cc + k) * 320 + 64 + cb];
                        unsigned long long ap;
                        ap = pack2(a0[k]);  fma2(acc[0][0], ap, b0); fma2(acc[0][1], ap, b1);
                        ap = pack2(a1[k]);  fma2(acc[1][0], ap, b0); fma2(acc[1][1], ap, b1);
                        ap = pack2(a2v[k]); fma2(acc[2][0], ap, b0); fma2(acc[2][1], ap, b1);
                        ap = pack2(a3[k]);  fma2(acc[3][0], ap, b0); fma2(acc[3][1], ap, b1);
                    }
                }
                #pragma unroll 1
                for (int i = 0; i < 4; i++) {
                    int el = e0 + i;
                    int r = sRecv[el];
                    if (r < 0) continue;
                    int s = sSend[el];
                    float4 Yv = sY[el];
                    const float4* xp = &d_x[(size_t)s * CCH + cb];
                    float4 xs0 = xp[0];
                    float4 xs1 = xp[1];
                    float2 t0 = unpack2(acc[i][0]);
                    float2 t1 = unpack2(acc[i][1]);
                    float* dst = (float*)&d_M[(size_t)r * CCH + cb];
                    emit_msg<true>(dst,     xs0, Yv, t0.x, t1.x, 0, 0, 0);
                    emit_msg<true>(dst + 4, xs1, Yv, t0.y, t1.y, 0, 0, 0);
                }
            } else {
                unsigned long long acc[4][5];
                #pragma unroll
                for (int i = 0; i < 4; i++)
                    #pragma unroll
                    for (int p = 0; p < 5; p++) acc[i][p] = 0ull;
                #pragma unroll 2
                for (int cc = 0; cc < 64; cc += 2) {
                    float2 a0 = *(const float2*)&sHb[(e0 + 0) * HSTR + cc];
                    float2 a1 = *(const float2*)&sHb[(e0 + 1) * HSTR + cc];
                    float2 a2v = *(const float2*)&sHb[(e0 + 2) * HSTR + cc];
                    float2 a3 = *(const float2*)&sHb[(e0 + 3) * HSTR + cc];
                    #pragma unroll
                    for (int k = 0; k < 2; k++) {
                        unsigned long long b0 = *(const unsigned long long*)&sW3[(cc + k) * 320 + cb];
                        unsigned long long b1 = *(const unsigned long long*)&sW3[(cc + k) * 320 + 64 + cb];
                        unsigned long long b2 = *(const unsigned long long*)&sW3[(cc + k) * 320 + 128 + cb];
                        unsigned long long b3 = *(const unsigned long long*)&sW3[(cc + k) * 320 + 192 + cb];
                        unsigned long long b4 = *(const unsigned long long*)&sW3[(cc + k) * 320 + 256 + cb];
                        unsigned long long ap;
                        ap = pack2(k ? a0.y : a0.x);
                        fma2(acc[0][0], ap, b0); fma2(acc[0][1], ap, b1); fma2(acc[0][2], ap, b2);
                        fma2(acc[0][3], ap, b3); fma2(acc[0][4], ap, b4);
                        ap = pack2(k ? a1.y : a1.x);
                        fma2(acc[1][0], ap, b0); fma2(acc[1][1], ap, b1); fma2(acc[1][2], ap, b2);
                        fma2(acc[1][3], ap, b3); fma2(acc[1][4], ap, b4);
                        ap = pack2(k ? a2v.y : a2v.x);
                        fma2(acc[2][0], ap, b0); fma2(acc[2][1], ap, b1); fma2(acc[2][2], ap, b2);
                        fma2(acc[2][3], ap, b3); fma2(acc[2][4], ap, b4);
                        ap = pack2(k ? a3.y : a3.x);
                        fma2(acc[3][0], ap, b0); fma2(acc[3][1], ap, b1); fma2(acc[3][2], ap, b2);
                        fma2(acc[3][3], ap, b3); fma2(acc[3][4], ap, b4);
                    }
                }
                #pragma unroll 1
                for (int i = 0; i < 4; i++) {
                    int el = e0 + i;
                    int r = sRecv[el];
                    if (r < 0) continue;
                    int s = sSend[el];
                    float4 Yv = sY[el];
                    const float4* xp = &d_x[(size_t)s * CCH + cb];
                    float4 xs0 = xp[0];
                    float4 xs1 = xp[1];
                    float2 t0 = unpack2(acc[i][0]);
                    float2 t1 = unpack2(acc[i][1]);
                    float2 t2 = unpack2(acc[i][2]);
                    float2 t3 = unpack2(acc[i][3]);
                    float2 t4 = unpack2(acc[i][4]);
                    float* dst = (float*)&d_M[(size_t)r * CCH + cb];
                    emit_msg<false>(dst,     xs0, Yv, t0.x, t1.x, t2.x, t3.x, t4.x);
                    emit_msg<false>(dst + 4, xs1, Yv, t0.y, t1.y, t2.y, t3.y, t4.y);
                }
            }
        }
    }
}

// ---------------------------------------------------------------------------
// Fused post(l0)+up(l1) / final post
// ---------------------------------------------------------------------------
#define SMP_LW0 0
#define SMP_LW1 4096
#define SMP_PL0 8192
#define SMP_PL1 12288
#define SMP_PW0 16384
#define SMP_PW1 17152
#define SMP_A   17664
#define SMP_B   18688
#define SMP_TOT 19712   // floats

template<bool FINAL>
__global__ void __launch_bounds__(256) k_post(
    const int* __restrict__ species,
    const float* __restrict__ LW0g, const float* __restrict__ LW1g,
    const float* __restrict__ PW0g, const float* __restrict__ PW1g,
    const float* __restrict__ PL0g, const float* __restrict__ PL1g,
    float4* __restrict__ out, int N_)
{
    extern __shared__ float sm[];
    float* sLW0 = sm + SMP_LW0;
    float* sLW1 = sm + SMP_LW1;
    float* sPL0 = sm + SMP_PL0;
    float* sPL1 = sm + SMP_PL1;
    float* sPW0 = sm + SMP_PW0;
    float* sPW1 = sm + SMP_PW1;
    float4* sA = (float4*)(sm + SMP_A);
    float4* sB = (float4*)(sm + SMP_B);
    int tid = threadIdx.x;
    const float INV_SQRT3 = 0.5773502691896258f;
    for (int i = tid; i < 4096; i += 256) {
        sLW0[i] = LW0g[i];
        sLW1[i] = LW1g[i];
        sPL0[i] = PL0g[i];
        sPL1[i] = PL1g[i];
    }
    for (int i = tid; i < 768; i += 256) sPW0[i] = PW0g[i];
    for (int i = tid; i < 512; i += 256) sPW1[i] = PW1g[i];
    __syncthreads();

    int base = blockIdx.x * 64;
    int c = tid & 63, sub = tid >> 6;
    for (int g = 0; g < 16; g++) {
        int n = base + g * 4 + sub;
        bool act = n < N_;
        if (act) {
            float4 mv = d_M[(size_t)n * CCH + c];
            mv.x *= 0.0625f; mv.y *= 0.0625f; mv.z *= 0.0625f; mv.w *= 0.0625f;
            sA[sub * CCH + c] = mv;
        }
        __syncthreads();
        if (act) {
            float h0 = 0, h1x = 0, h1y = 0, h1z = 0;
            const float4* ar = &sA[sub * CCH];
            #pragma unroll 8
            for (int cc = 0; cc < 64; cc++) {
                float4 a = ar[cc];
                float w0 = sLW0[cc * 64 + c];
                float w1 = sLW1[cc * 64 + c];
                h0 += a.x * w0;
                h1x += a.y * w1;
                h1y += a.z * w1;
                h1z += a.w * w1;
            }
            int sp = species[n];
            float nrm = (h1x * h1x + h1y * h1y + h1z * h1z) * INV_SQRT3;
            const float* p0 = &sPW0[sp * 192 + c];
            float b0 = p0[0] * h0 + p0[64] * h0 * h0 + p0[128] * nrm;
            const float* p1 = &sPW1[sp * 128 + c];
            float q = p1[0] + p1[64] * h0;
            sB[sub * CCH + c] = make_float4(b0, q * h1x, q * h1y, q * h1z);
        }
        __syncthreads();
        if (act) {
            float o0 = 0, o1 = 0, o2 = 0, o3 = 0;
            const float4* br = &sB[sub * CCH];
            #pragma unroll 8
            for (int cc = 0; cc < 64; cc++) {
                float4 b = br[cc];
                float w0 = sPL0[cc * 64 + c];
                float w1 = sPL1[cc * 64 + c];
                o0 += b.x * w0;
                o1 += b.y * w1;
                o2 += b.z * w1;
                o3 += b.w * w1;
            }
            if (FINAL) {
                out[(size_t)n * CCH + c] = make_float4(o0, o1, o2, o3);
            } else {
                d_x[(size_t)n * CCH + c] = make_float4(o0, o1, o2, o3);
                d_M[(size_t)n * CCH + c] = make_float4(0, 0, 0, 0);
            }
        }
        __syncthreads();
    }
}

// ---------------------------------------------------------------------------
extern "C" void kernel_launch(void* const* d_in, const int* in_sizes, int n_in,
                              void* d_out, int out_size) {
    const float* positions    = (const float*)d_in[0];
    const int*   species      = (const int*)d_in[1];
    const int*   edge_index   = (const int*)d_in[2];
    const float* node_embed_W = (const float*)d_in[3];
    const float* lin_up_W0    = (const float*)d_in[4];
    const float* lin_up_W1    = (const float*)d_in[5];
    const float* mlp_W1       = (const float*)d_in[6];
    const float* mlp_W2       = (const float*)d_in[7];
    const float* mlp_W3       = (const float*)d_in[8];
    const float* lin_W0       = (const float*)d_in[9];
    const float* lin_W1       = (const float*)d_in[10];
    const float* prod_W0      = (const float*)d_in[11];
    const float* prod_W1      = (const float*)d_in[12];
    const float* prod_lin_W0  = (const float*)d_in[13];
    const float* prod_lin_W1  = (const float*)d_in[14];

    int N_ = in_sizes[0] / 3;
    int E_ = in_sizes[2] / 2;

    size_t smemE = (size_t)SME_TOT * 4;
    size_t smemP = (size_t)SMP_TOT * 4;
    cudaFuncSetAttribute(k_edge<true>,  cudaFuncAttributeMaxDynamicSharedMemorySize, (int)smemE);
    cudaFuncSetAttribute(k_edge<false>, cudaFuncAttributeMaxDynamicSharedMemorySize, (int)smemE);
    cudaFuncSetAttribute(k_post<true>,  cudaFuncAttributeMaxDynamicSharedMemorySize, (int)smemP);
    cudaFuncSetAttribute(k_post<false>, cudaFuncAttributeMaxDynamicSharedMemorySize, (int)smemP);

    k_geom<<<(E_ + 255) / 256, 256>>>(positions, edge_index, E_);
    k_prepw<<<1, 256>>>(node_embed_W, lin_up_W0,
                        prod_lin_W0, lin_up_W0 + 4096,
                        prod_lin_W1, lin_up_W1 + 4096);
    k_seed<<<(N_ * CCH + 255) / 256, 256>>>(species, N_);

    void* p0;
    void* p1;
    cudaGetSymbolAddress(&p0, d_W0c);
    cudaGetSymbolAddress(&p1, d_W1c);
    const float* W0c_sym = (const float*)p0;
    const float* W1c_sym = (const float*)p1;

    // layer 0
    k_edge<true><<<EGRID, ETHREADS, smemE>>>(edge_index, mlp_W1, mlp_W2, mlp_W3, E_);
    k_post<false><<<(N_ + 63) / 64, 256, smemP>>>(
        species, lin_W0, lin_W1, prod_W0, prod_W1,
        W0c_sym, W1c_sym, nullptr, N_);

    // layer 1
    k_edge<false><<<EGRID, ETHREADS, smemE>>>(
        edge_index, mlp_W1 + 512, mlp_W2 + 4096, mlp_W3 + 20480, E_);
    k_post<true><<<(N_ + 63) / 64, 256, smemP>>>(
        species, lin_W0 + 4096, lin_W1 + 4096,
        prod_W0 + 768, prod_W1 + 512,
        prod_lin_W0 + 4096, prod_lin_W1 + 4096,
        (float4*)d_out, N_);
}

// round 9
// speedup vs baseline: 1.0779x; 1.0779x over previous
#include <cuda_runtime.h>
#include <cstdint>

#define N_MAX 25000
#define E_MAX 400000
#define CCH 64
#define TILE 128
#define ETHREADS 1024
#define EGRID 148

static __device__ float4 d_x[N_MAX * CCH];   // up-projected  [N][C][4]
static __device__ float4 d_M[N_MAX * CCH];   // scatter accum [N][C][4]
static __device__ float  d_ef[E_MAX * 8];    // edge bessel feats
static __device__ float4 d_Y[E_MAX];         // sqrt3 * unit vec (w unused)
static __device__ float  d_U[4 * CCH];       // embW @ lin_up_W0[0]
static __device__ float  d_W0c[CCH * CCH];   // prod_lin_W0[0] @ lin_up_W0[1]
static __device__ float  d_W1c[CCH * CCH];   // prod_lin_W1[0] @ lin_up_W1[1]

__device__ __forceinline__ float silu_f(float v) {
    return v / (1.0f + __expf(-v));
}
__device__ __forceinline__ unsigned long long pack2(float x) {
    unsigned long long r;
    asm("mov.b64 %0, {%1, %1};" : "=l"(r) : "f"(x));
    return r;
}
__device__ __forceinline__ void fma2(unsigned long long &d, unsigned long long a, unsigned long long b) {
    asm("fma.rn.f32x2 %0, %1, %2, %0;" : "+l"(d) : "l"(a), "l"(b));
}
__device__ __forceinline__ float2 unpack2(unsigned long long v) {
    float2 r;
    asm("mov.b64 {%0, %1}, %2;" : "=f"(r.x), "=f"(r.y) : "l"(v));
    return r;
}

// ---------------------------------------------------------------------------
// Per-edge geometry (accurate sinf — MUFU __sinf is NOT accurate at 8pi)
// ---------------------------------------------------------------------------
__global__ void k_geom(const float* __restrict__ pos, const int* __restrict__ ei, int E_) {
    int e = blockIdx.x * blockDim.x + threadIdx.x;
    if (e >= E_) return;
    int s = ei[e];
    int r_ = ei[E_ + e];
    float vx = pos[3*s + 0] - pos[3*r_ + 0];
    float vy = pos[3*s + 1] - pos[3*r_ + 1];
    float vz = pos[3*s + 2] - pos[3*r_ + 2];
    float rr = sqrtf(vx*vx + vy*vy + vz*vz);
    rr = fmaxf(rr, 1e-6f);
    float inv_r = 1.0f / rr;
    const float SQRT3 = 1.7320508075688772f;
    float4 Y;
    Y.x = SQRT3 * vx * inv_r;
    Y.y = SQRT3 * vy * inv_r;
    Y.z = SQRT3 * vz * inv_r;
    Y.w = 0.0f;
    d_Y[e] = Y;
    float x = rr * 0.2f;
    float x2 = x * x;
    float x6 = x2 * x2 * x2;
    float fc = 1.0f - 28.0f*x6 + 48.0f*x6*x - 21.0f*x6*x2;
    fc = (x < 1.0f) ? fc : 0.0f;
    const float BC = 0.6324555320336759f;      // sqrt(2/5)
    const float PI_O_R = 0.6283185307179586f;  // pi/5
    float pref = BC * inv_r * fc;
    float ef[8];
    #pragma unroll
    for (int k = 0; k < 8; k++)
        ef[k] = pref * sinf((float)(k + 1) * PI_O_R * rr);
    float4* dst = (float4*)(d_ef + (size_t)e * 8);
    dst[0] = make_float4(ef[0], ef[1], ef[2], ef[3]);
    dst[1] = make_float4(ef[4], ef[5], ef[6], ef[7]);
}

// ---------------------------------------------------------------------------
// Weight prep (single block)
// ---------------------------------------------------------------------------
__global__ void __launch_bounds__(256) k_prepw(
    const float* __restrict__ embW, const float* __restrict__ LU0_l0,
    const float* __restrict__ PL0_l0, const float* __restrict__ LU0_l1,
    const float* __restrict__ PL1_l0, const float* __restrict__ LU1_l1)
{
    int tid = threadIdx.x;
    {
        int s = tid >> 6, j = tid & 63;
        float acc = 0.0f;
        for (int k = 0; k < 64; k++) acc += embW[s * 64 + k] * LU0_l0[k * 64 + j];
        d_U[tid] = acc;
    }
    for (int t = tid; t < 4096; t += 256) {
        int i = t >> 6, j = t & 63;
        float a0 = 0.0f, a1 = 0.0f;
        for (int k = 0; k < 64; k++) {
            a0 += PL0_l0[i * 64 + k] * LU0_l1[k * 64 + j];
            a1 += PL1_l0[i * 64 + k] * LU1_l1[k * 64 + j];
        }
        d_W0c[t] = a0;
        d_W1c[t] = a1;
    }
}

// ---------------------------------------------------------------------------
// Layer-0 seed: x = row-select of U (h1 == 0), zero M
// ---------------------------------------------------------------------------
__global__ void k_seed(const int* __restrict__ species, int N_) {
    int idx = blockIdx.x * blockDim.x + threadIdx.x;
    if (idx >= N_ * CCH) return;
    int n = idx >> 6, c = idx & 63;
    int sp = species[n];
    d_x[idx] = make_float4(d_U[sp * CCH + c], 0.0f, 0.0f, 0.0f);
    d_M[idx] = make_float4(0, 0, 0, 0);
}

// ---------------------------------------------------------------------------
// Persistent fused edge kernel (1024 threads, 32 warps): SMEM-resident
// weights, 128-edge tiles, fused MLP + tensor product + red scatter.
// Layer-1 phase D is split into two path groups (additive partial messages)
// to keep per-thread accumulators at <= 24 u64 = 48 regs: NO spills at the
// 64-reg/thread cap.
// ---------------------------------------------------------------------------
#define SME_W1   0
#define SME_W2   512
#define SME_W3   4608
#define SME_HA   25088
#define SME_HB   33280
#define SME_EF   41472
#define SME_Y    42496
#define SME_SND  43008
#define SME_RCV  43136
#define SME_TOT  43264   // floats (169 KB)

// paths 0,1 partial: m0 = t0*xs0 ; m1 = t1*xs0*Y
__device__ __forceinline__ void emit_msgA(float* dst, float xs0, float4 Yv,
                                          float t0, float t1) {
    float a = t1 * xs0;
    asm volatile("red.global.add.v4.f32 [%0], {%1,%2,%3,%4};"
                 :: "l"(dst), "f"(t0 * xs0), "f"(a * Yv.x), "f"(a * Yv.y), "f"(a * Yv.z)
                 : "memory");
}

// paths 2,3,4 partial: m0 = t3*(xs1.Y)/sqrt3 ; m1 = t2*xs1 + t4*(xs1 x Y)/sqrt2
__device__ __forceinline__ void emit_msgB(float* dst, float4 xs, float4 Yv,
                                          float t2, float t3, float t4) {
    const float INV_SQRT3 = 0.5773502691896258f;
    const float INV_SQRT2 = 0.7071067811865475f;
    float dotv = xs.y * Yv.x + xs.z * Yv.y + xs.w * Yv.z;
    float m0 = t3 * dotv * INV_SQRT3;
    float cx = xs.z * Yv.z - xs.w * Yv.y;
    float cy = xs.w * Yv.x - xs.y * Yv.z;
    float cz = xs.y * Yv.y - xs.z * Yv.x;
    float t4s = t4 * INV_SQRT2;
    float m1x = t2 * xs.y + t4s * cx;
    float m1y = t2 * xs.z + t4s * cy;
    float m1z = t2 * xs.w + t4s * cz;
    asm volatile("red.global.add.v4.f32 [%0], {%1,%2,%3,%4};"
                 :: "l"(dst), "f"(m0), "f"(m1x), "f"(m1y), "f"(m1z)
                 : "memory");
}

template<bool FIRST>
__global__ void __launch_bounds__(ETHREADS, 1) k_edge(
    const int* __restrict__ ei,
    const float* __restrict__ W1g, const float* __restrict__ W2g,
    const float* __restrict__ W3g, int E_)
{
    extern __shared__ float sm[];
    float* sW1 = sm + SME_W1;
    float* sW2 = sm + SME_W2;
    float* sW3 = sm + SME_W3;
    float* sHa = sm + SME_HA;
    float* sHb = sm + SME_HB;
    float* sEF = sm + SME_EF;
    float4* sY = (float4*)(sm + SME_Y);
    int* sSend = (int*)(sm + SME_SND);
    int* sRecv = (int*)(sm + SME_RCV);
    const int tid = threadIdx.x;

    // one-time weight load (persistent block)
    for (int i = tid; i < 512; i += ETHREADS) sW1[i] = W1g[i];
    for (int i = tid; i < 4096; i += ETHREADS) sW2[i] = W2g[i];
    for (int i = tid; i < 20480; i += ETHREADS) sW3[i] = W3g[i];

    int nTiles = (E_ + TILE - 1) / TILE;
    for (int t = blockIdx.x; t < nTiles; t += gridDim.x) {
        long long base = (long long)t * TILE;
        __syncthreads();   // weights ready (iter 0) / prev tile consumers done
        if (tid < 256) {
            long long e = base + (tid >> 1);
            float4 v = make_float4(0, 0, 0, 0);
            if (e < E_) v = ((const float4*)d_ef)[e * 2 + (tid & 1)];
            ((float4*)sEF)[tid] = v;
        } else if (tid < 384) {
            int i = tid - 256;
            long long e = base + i;
            float4 y = make_float4(0, 0, 0, 0);
            if (e < E_) y = d_Y[e];
            sY[i] = y;
        } else if (tid < 512) {
            int i = tid - 384;
            long long e = base + i;
            int s = 0, r = -1;
            if (e < E_) { s = ei[e]; r = ei[E_ + e]; }
            sSend[i] = s;
            sRecv[i] = r;
        }
        __syncthreads();

        // Phase B: H1 = silu(EF @ W1)   [128x8]@[8x64]
        #pragma unroll
        for (int i = 0; i < (TILE * 64) / ETHREADS; i++) {
            int idx = tid + ETHREADS * i;
            int e = idx >> 6, j = idx & 63;
            float acc = 0.0f;
            #pragma unroll
            for (int k = 0; k < 8; k++) acc += sEF[e * 8 + k] * sW1[k * 64 + j];
            sHa[idx] = silu_f(acc);
        }
        __syncthreads();

        // Phase C: H2 = silu(H1 @ W2)  [128x64]@[64x64], 2 edges x 4 cols
        {
            int e0 = (tid >> 4) << 1;
            int j0 = (tid & 15) << 2;
            unsigned long long acc[2][2] = {};
            #pragma unroll 4
            for (int cc = 0; cc < 64; cc++) {
                const unsigned long long* bp = (const unsigned long long*)&sW2[cc * 64 + j0];
                unsigned long long b0 = bp[0], b1 = bp[1];
                #pragma unroll
                for (int i = 0; i < 2; i++) {
                    unsigned long long a2 = pack2(sHa[(e0 + i) * 64 + cc]);
                    fma2(acc[i][0], a2, b0);
                    fma2(acc[i][1], a2, b1);
                }
            }
            #pragma unroll
            for (int i = 0; i < 2; i++) {
                float2 p0 = unpack2(acc[i][0]);
                float2 p1 = unpack2(acc[i][1]);
                float* dst = &sHb[(e0 + i) * 64 + j0];
                dst[0] = silu_f(p0.x);
                dst[1] = silu_f(p0.y);
                dst[2] = silu_f(p1.x);
                dst[3] = silu_f(p1.y);
            }
        }
        __syncthreads();

        // Phase D+E fused. Thread tile: 4 edges x 2 channels.
        {
            int eb = (tid >> 5) << 2;
            int cb = (tid & 31) << 1;

            // --- group A: paths 0,1 (both layers) ---
            {
                unsigned long long acc[4][2];
                #pragma unroll
                for (int ii = 0; ii < 4; ii++) { acc[ii][0] = 0ull; acc[ii][1] = 0ull; }
                #pragma unroll 2
                for (int cc = 0; cc < 64; cc++) {
                    const float* wrow = &sW3[cc * 320 + cb];
                    unsigned long long b0 = *(const unsigned long long*)(wrow);
                    unsigned long long b1 = *(const unsigned long long*)(wrow + 64);
                    #pragma unroll
                    for (int ii = 0; ii < 4; ii++) {
                        unsigned long long a2 = pack2(sHb[(eb + ii) * 64 + cc]);
                        fma2(acc[ii][0], a2, b0);
                        fma2(acc[ii][1], a2, b1);
                    }
                }
                #pragma unroll 1
                for (int ii = 0; ii < 4; ii++) {
                    int el = eb + ii;
                    int r = sRecv[el];
                    if (r < 0) continue;
                    int s = sSend[el];
                    float4 Yv = sY[el];
                    const float4* xp = &d_x[(size_t)s * CCH + cb];
                    float xs0a = xp[0].x;
                    float xs0b = xp[1].x;
                    float2 t0 = unpack2(acc[ii][0]);
                    float2 t1 = unpack2(acc[ii][1]);
                    float* dst = (float*)&d_M[(size_t)r * CCH + cb];
                    emit_msgA(dst,     xs0a, Yv, t0.x, t1.x);
                    emit_msgA(dst + 4, xs0b, Yv, t0.y, t1.y);
                }
            }

            // --- group B: paths 2,3,4 (layer 1 only) ---
            if (!FIRST) {
                unsigned long long acc[4][3];
                #pragma unroll
                for (int ii = 0; ii < 4; ii++) {
                    acc[ii][0] = 0ull; acc[ii][1] = 0ull; acc[ii][2] = 0ull;
                }
                #pragma unroll 2
                for (int cc = 0; cc < 64; cc++) {
                    const float* wrow = &sW3[cc * 320 + cb];
                    unsigned long long b2 = *(const unsigned long long*)(wrow + 128);
                    unsigned long long b3 = *(const unsigned long long*)(wrow + 192);
                    unsigned long long b4 = *(const unsigned long long*)(wrow + 256);
                    #pragma unroll
                    for (int ii = 0; ii < 4; ii++) {
                        unsigned long long a2 = pack2(sHb[(eb + ii) * 64 + cc]);
                        fma2(acc[ii][0], a2, b2);
                        fma2(acc[ii][1], a2, b3);
                        fma2(acc[ii][2], a2, b4);
                    }
                }
                #pragma unroll 1
                for (int ii = 0; ii < 4; ii++) {
                    int el = eb + ii;
                    int r = sRecv[el];
                    if (r < 0) continue;
                    int s = sSend[el];
                    float4 Yv = sY[el];
                    const float4* xp = &d_x[(size_t)s * CCH + cb];
                    float4 xsa = xp[0];
                    float4 xsb = xp[1];
                    float2 t2 = unpack2(acc[ii][0]);
                    float2 t3 = unpack2(acc[ii][1]);
                    float2 t4 = unpack2(acc[ii][2]);
                    float* dst = (float*)&d_M[(size_t)r * CCH + cb];
                    emit_msgB(dst,     xsa, Yv, t2.x, t3.x, t4.x);
                    emit_msgB(dst + 4, xsb, Yv, t2.y, t3.y, t4.y);
                }
            }
        }
    }
}

// ---------------------------------------------------------------------------
// Fused post(l0)+up(l1) / final post
// ---------------------------------------------------------------------------
#define SMP_LW0 0
#define SMP_LW1 4096
#define SMP_PL0 8192
#define SMP_PL1 12288
#define SMP_PW0 16384
#define SMP_PW1 17152
#define SMP_A   17664
#define SMP_B   18688
#define SMP_TOT 19712   // floats

template<bool FINAL>
__global__ void __launch_bounds__(256) k_post(
    const int* __restrict__ species,
    const float* __restrict__ LW0g, const float* __restrict__ LW1g,
    const float* __restrict__ PW0g, const float* __restrict__ PW1g,
    const float* __restrict__ PL0g, const float* __restrict__ PL1g,
    float4* __restrict__ out, int N_)
{
    extern __shared__ float sm[];
    float* sLW0 = sm + SMP_LW0;
    float* sLW1 = sm + SMP_LW1;
    float* sPL0 = sm + SMP_PL0;
    float* sPL1 = sm + SMP_PL1;
    float* sPW0 = sm + SMP_PW0;
    float* sPW1 = sm + SMP_PW1;
    float4* sA = (float4*)(sm + SMP_A);
    float4* sB = (float4*)(sm + SMP_B);
    int tid = threadIdx.x;
    const float INV_SQRT3 = 0.5773502691896258f;
    for (int i = tid; i < 4096; i += 256) {
        sLW0[i] = LW0g[i];
        sLW1[i] = LW1g[i];
        sPL0[i] = PL0g[i];
        sPL1[i] = PL1g[i];
    }
    for (int i = tid; i < 768; i += 256) sPW0[i] = PW0g[i];
    for (int i = tid; i < 512; i += 256) sPW1[i] = PW1g[i];
    __syncthreads();

    int base = blockIdx.x * 64;
    int c = tid & 63, sub = tid >> 6;
    for (int g = 0; g < 16; g++) {
        int n = base + g * 4 + sub;
        bool act = n < N_;
        if (act) {
            float4 mv = d_M[(size_t)n * CCH + c];
            mv.x *= 0.0625f; mv.y *= 0.0625f; mv.z *= 0.0625f; mv.w *= 0.0625f;
            sA[sub * CCH + c] = mv;
        }
        __syncthreads();
        if (act) {
            float h0 = 0, h1x = 0, h1y = 0, h1z = 0;
            const float4* ar = &sA[sub * CCH];
            #pragma unroll 8
            for (int cc = 0; cc < 64; cc++) {
                float4 a = ar[cc];
                float w0 = sLW0[cc * 64 + c];
                float w1 = sLW1[cc * 64 + c];
                h0 += a.x * w0;
                h1x += a.y * w1;
                h1y += a.z * w1;
                h1z += a.w * w1;
            }
            int sp = species[n];
            float nrm = (h1x * h1x + h1y * h1y + h1z * h1z) * INV_SQRT3;
            const float* p0 = &sPW0[sp * 192 + c];
            float b0 = p0[0] * h0 + p0[64] * h0 * h0 + p0[128] * nrm;
            const float* p1 = &sPW1[sp * 128 + c];
            float q = p1[0] + p1[64] * h0;
            sB[sub * CCH + c] = make_float4(b0, q * h1x, q * h1y, q * h1z);
        }
        __syncthreads();
        if (act) {
            float o0 = 0, o1 = 0, o2 = 0, o3 = 0;
            const float4* br = &sB[sub * CCH];
            #pragma unroll 8
            for (int cc = 0; cc < 64; cc++) {
                float4 b = br[cc];
                float w0 = sPL0[cc * 64 + c];
                float w1 = sPL1[cc * 64 + c];
                o0 += b.x * w0;
                o1 += b.y * w1;
                o2 += b.z * w1;
                o3 += b.w * w1;
            }
            if (FINAL) {
                out[(size_t)n * CCH + c] = make_float4(o0, o1, o2, o3);
            } else {
                d_x[(size_t)n * CCH + c] = make_float4(o0, o1, o2, o3);
                d_M[(size_t)n * CCH + c] = make_float4(0, 0, 0, 0);
            }
        }
        __syncthreads();
    }
}

// ---------------------------------------------------------------------------
extern "C" void kernel_launch(void* const* d_in, const int* in_sizes, int n_in,
                              void* d_out, int out_size) {
    const float* positions    = (const float*)d_in[0];
    const int*   species      = (const int*)d_in[1];
    const int*   edge_index   = (const int*)d_in[2];
    const float* node_embed_W = (const float*)d_in[3];
    const float* lin_up_W0    = (const float*)d_in[4];
    const float* lin_up_W1    = (const float*)d_in[5];
    const float* mlp_W1       = (const float*)d_in[6];
    const float* mlp_W2       = (const float*)d_in[7];
    const float* mlp_W3       = (const float*)d_in[8];
    const float* lin_W0       = (const float*)d_in[9];
    const float* lin_W1       = (const float*)d_in[10];
    const float* prod_W0      = (const float*)d_in[11];
    const float* prod_W1      = (const float*)d_in[12];
    const float* prod_lin_W0  = (const float*)d_in[13];
    const float* prod_lin_W1  = (const float*)d_in[14];

    int N_ = in_sizes[0] / 3;
    int E_ = in_sizes[2] / 2;

    size_t smemE = (size_t)SME_TOT * 4;
    size_t smemP = (size_t)SMP_TOT * 4;
    cudaFuncSetAttribute(k_edge<true>,  cudaFuncAttributeMaxDynamicSharedMemorySize, (int)smemE);
    cudaFuncSetAttribute(k_edge<false>, cudaFuncAttributeMaxDynamicSharedMemorySize, (int)smemE);
    cudaFuncSetAttribute(k_post<true>,  cudaFuncAttributeMaxDynamicSharedMemorySize, (int)smemP);
    cudaFuncSetAttribute(k_post<false>, cudaFuncAttributeMaxDynamicSharedMemorySize, (int)smemP);

    k_geom<<<(E_ + 255) / 256, 256>>>(positions, edge_index, E_);
    k_prepw<<<1, 256>>>(node_embed_W, lin_up_W0,
                        prod_lin_W0, lin_up_W0 + 4096,
                        prod_lin_W1, lin_up_W1 + 4096);
    k_seed<<<(N_ * CCH + 255) / 256, 256>>>(species, N_);

    void* p0;
    void* p1;
    cudaGetSymbolAddress(&p0, d_W0c);
    cudaGetSymbolAddress(&p1, d_W1c);
    const float* W0c_sym = (const float*)p0;
    const float* W1c_sym = (const float*)p1;

    // layer 0
    k_edge<true><<<EGRID, ETHREADS, smemE>>>(edge_index, mlp_W1, mlp_W2, mlp_W3, E_);
    k_post<false><<<(N_ + 63) / 64, 256, smemP>>>(
        species, lin_W0, lin_W1, prod_W0, prod_W1,
        W0c_sym, W1c_sym, nullptr, N_);

    // layer 1
    k_edge<false><<<EGRID, ETHREADS, smemE>>>(
        edge_index, mlp_W1 + 512, mlp_W2 + 4096, mlp_W3 + 20480, E_);
    k_post<true><<<(N_ + 63) / 64, 256, smemP>>>(
        species, lin_W0 + 4096, lin_W1 + 4096,
        prod_W0 + 768, prod_W1 + 512,
        prod_lin_W0 + 4096, prod_lin_W1 + 4096,
        (float4*)d_out, N_);
}

// round 11
// speedup vs baseline: 1.1545x; 1.0710x over previous
#include <cuda_runtime.h>
#include <cstdint>

#define N_MAX 25000
#define E_MAX 400000
#define CCH 64
#define ETHREADS 512
#define EGRID 148

static __device__ float4 d_x[N_MAX * CCH];   // up-projected  [N][C][4]
static __device__ float4 d_M[N_MAX * CCH];   // scatter accum [N][C][4]
static __device__ float  d_ef[E_MAX * 8];    // edge bessel feats
static __device__ float4 d_Y[E_MAX];         // sqrt3 * unit vec (w unused)
static __device__ float  d_U[4 * CCH];       // embW @ lin_up_W0[0]
static __device__ float  d_W0c[CCH * CCH];   // prod_lin_W0[0] @ lin_up_W0[1]
static __device__ float  d_W1c[CCH * CCH];   // prod_lin_W1[0] @ lin_up_W1[1]

__device__ __forceinline__ float silu_f(float v) {
    return v / (1.0f + __expf(-v));
}
__device__ __forceinline__ unsigned long long pack2(float x) {
    unsigned long long r;
    asm("mov.b64 %0, {%1, %1};" : "=l"(r) : "f"(x));
    return r;
}
__device__ __forceinline__ void fma2(unsigned long long &d, unsigned long long a, unsigned long long b) {
    asm("fma.rn.f32x2 %0, %1, %2, %0;" : "+l"(d) : "l"(a), "l"(b));
}
__device__ __forceinline__ float2 unpack2(unsigned long long v) {
    float2 r;
    asm("mov.b64 {%0, %1}, %2;" : "=f"(r.x), "=f"(r.y) : "l"(v));
    return r;
}

// ---------------------------------------------------------------------------
// Per-edge geometry (accurate sinf — MUFU __sinf is NOT accurate at 8pi)
// ---------------------------------------------------------------------------
__global__ void k_geom(const float* __restrict__ pos, const int* __restrict__ ei, int E_) {
    int e = blockIdx.x * blockDim.x + threadIdx.x;
    if (e >= E_) return;
    int s = ei[e];
    int r_ = ei[E_ + e];
    float vx = pos[3*s + 0] - pos[3*r_ + 0];
    float vy = pos[3*s + 1] - pos[3*r_ + 1];
    float vz = pos[3*s + 2] - pos[3*r_ + 2];
    float rr = sqrtf(vx*vx + vy*vy + vz*vz);
    rr = fmaxf(rr, 1e-6f);
    float inv_r = 1.0f / rr;
    const float SQRT3 = 1.7320508075688772f;
    float4 Y;
    Y.x = SQRT3 * vx * inv_r;
    Y.y = SQRT3 * vy * inv_r;
    Y.z = SQRT3 * vz * inv_r;
    Y.w = 0.0f;
    d_Y[e] = Y;
    float x = rr * 0.2f;
    float x2 = x * x;
    float x6 = x2 * x2 * x2;
    float fc = 1.0f - 28.0f*x6 + 48.0f*x6*x - 21.0f*x6*x2;
    fc = (x < 1.0f) ? fc : 0.0f;
    const float BC = 0.6324555320336759f;      // sqrt(2/5)
    const float PI_O_R = 0.6283185307179586f;  // pi/5
    float pref = BC * inv_r * fc;
    float ef[8];
    #pragma unroll
    for (int k = 0; k < 8; k++)
        ef[k] = pref * sinf((float)(k + 1) * PI_O_R * rr);
    float4* dst = (float4*)(d_ef + (size_t)e * 8);
    dst[0] = make_float4(ef[0], ef[1], ef[2], ef[3]);
    dst[1] = make_float4(ef[4], ef[5], ef[6], ef[7]);
}

// ---------------------------------------------------------------------------
// Weight prep (single block)
// ---------------------------------------------------------------------------
__global__ void __launch_bounds__(256) k_prepw(
    const float* __restrict__ embW, const float* __restrict__ LU0_l0,
    const float* __restrict__ PL0_l0, const float* __restrict__ LU0_l1,
    const float* __restrict__ PL1_l0, const float* __restrict__ LU1_l1)
{
    int tid = threadIdx.x;
    {
        int s = tid >> 6, j = tid & 63;
        float acc = 0.0f;
        for (int k = 0; k < 64; k++) acc += embW[s * 64 + k] * LU0_l0[k * 64 + j];
        d_U[tid] = acc;
    }
    for (int t = tid; t < 4096; t += 256) {
        int i = t >> 6, j = t & 63;
        float a0 = 0.0f, a1 = 0.0f;
        for (int k = 0; k < 64; k++) {
            a0 += PL0_l0[i * 64 + k] * LU0_l1[k * 64 + j];
            a1 += PL1_l0[i * 64 + k] * LU1_l1[k * 64 + j];
        }
        d_W0c[t] = a0;
        d_W1c[t] = a1;
    }
}

// ---------------------------------------------------------------------------
// Layer-0 seed: x = row-select of U (h1 == 0), zero M
// ---------------------------------------------------------------------------
__global__ void k_seed(const int* __restrict__ species, int N_) {
    int idx = blockIdx.x * blockDim.x + threadIdx.x;
    if (idx >= N_ * CCH) return;
    int n = idx >> 6, c = idx & 63;
    int sp = species[n];
    d_x[idx] = make_float4(d_U[sp * CCH + c], 0.0f, 0.0f, 0.0f);
    d_M[idx] = make_float4(0, 0, 0, 0);
}

// ---------------------------------------------------------------------------
// Persistent fused edge kernel, 512 threads (128-reg cap -> no spills).
//   FIRST (layer 0): TILE=128, D-tile 8 edges x 2 cols x 2 paths (64-reg acc)
//   !FIRST (layer 1): TILE=64,  D-tile 4 edges x 2 cols x 5 paths (80-reg acc)
// ---------------------------------------------------------------------------
#define SME_W1   0
#define SME_W2   512
#define SME_W3   4608
#define SME_HA   25088
#define SME_HB   33280
#define SME_EF   41472
#define SME_Y    42496
#define SME_SND  43008
#define SME_RCV  43136
#define SME_TOT  43264   // floats (169 KB)

template<bool FIRST>
__device__ __forceinline__ void emit_msg(float* dst, float4 xs, float4 Yv,
                                         float t0, float t1, float t2,
                                         float t3, float t4) {
    const float INV_SQRT3 = 0.5773502691896258f;
    const float INV_SQRT2 = 0.7071067811865475f;
    float m0, m1x, m1y, m1z;
    if (FIRST) {
        m0 = t0 * xs.x;
        float a = t1 * xs.x;
        m1x = a * Yv.x;
        m1y = a * Yv.y;
        m1z = a * Yv.z;
    } else {
        float dotv = xs.y * Yv.x + xs.z * Yv.y + xs.w * Yv.z;
        m0 = t0 * xs.x + t3 * dotv * INV_SQRT3;
        float cx = xs.z * Yv.z - xs.w * Yv.y;
        float cy = xs.w * Yv.x - xs.y * Yv.z;
        float cz = xs.y * Yv.y - xs.z * Yv.x;
        float a = t1 * xs.x;
        float t4s = t4 * INV_SQRT2;
        m1x = a * Yv.x + t2 * xs.y + t4s * cx;
        m1y = a * Yv.y + t2 * xs.z + t4s * cy;
        m1z = a * Yv.z + t2 * xs.w + t4s * cz;
    }
    asm volatile("red.global.add.v4.f32 [%0], {%1,%2,%3,%4};"
                 :: "l"(dst), "f"(m0), "f"(m1x), "f"(m1y), "f"(m1z)
                 : "memory");
}

template<bool FIRST>
__global__ void __launch_bounds__(ETHREADS, 1) k_edge(
    const int* __restrict__ ei,
    const float* __restrict__ W1g, const float* __restrict__ W2g,
    const float* __restrict__ W3g, int E_)
{
    extern __shared__ float sm[];
    float* sW1 = sm + SME_W1;
    float* sW2 = sm + SME_W2;
    float* sW3 = sm + SME_W3;
    float* sHa = sm + SME_HA;
    float* sHb = sm + SME_HB;
    float* sEF = sm + SME_EF;
    float4* sY = (float4*)(sm + SME_Y);
    int* sSend = (int*)(sm + SME_SND);
    int* sRecv = (int*)(sm + SME_RCV);
    const int tid = threadIdx.x;
    constexpr int T = FIRST ? 128 : 64;   // edges per tile
    constexpr int NB = FIRST ? 2 : 5;

    // one-time weight load (persistent block)
    for (int i = tid; i < 512; i += ETHREADS) sW1[i] = W1g[i];
    for (int i = tid; i < 4096; i += ETHREADS) sW2[i] = W2g[i];
    for (int i = tid; i < 20480; i += ETHREADS) sW3[i] = W3g[i];

    int nTiles = (E_ + T - 1) / T;
    for (int t = blockIdx.x; t < nTiles; t += gridDim.x) {
        long long base = (long long)t * T;
        __syncthreads();   // weights ready (iter 0) / prev tile consumers done
        if (tid < 2 * T) {
            long long e = base + (tid >> 1);
            float4 v = make_float4(0, 0, 0, 0);
            if (e < E_) v = ((const float4*)d_ef)[e * 2 + (tid & 1)];
            ((float4*)sEF)[tid] = v;
        } else if (tid < 3 * T) {
            int i = tid - 2 * T;
            long long e = base + i;
            float4 y = make_float4(0, 0, 0, 0);
            if (e < E_) y = d_Y[e];
            sY[i] = y;
        } else if (tid < 4 * T) {
            int i = tid - 3 * T;
            long long e = base + i;
            int s = 0, r = -1;
            if (e < E_) { s = ei[e]; r = ei[E_ + e]; }
            sSend[i] = s;
            sRecv[i] = r;
        }
        __syncthreads();

        // Phase B: H1 = silu(EF @ W1)   [T x 8]@[8 x 64]
        #pragma unroll
        for (int i = 0; i < (T * 64) / ETHREADS; i++) {
            int idx = tid + ETHREADS * i;
            int e = idx >> 6, j = idx & 63;
            float acc = 0.0f;
            #pragma unroll
            for (int k = 0; k < 8; k++) acc += sEF[e * 8 + k] * sW1[k * 64 + j];
            sHa[idx] = silu_f(acc);
        }
        __syncthreads();

        // Phase C: H2 = silu(H1 @ W2)  [T x 64]@[64 x 64]
        {
            constexpr int CE = FIRST ? 4 : 2;     // edges per thread
            int e0 = (tid >> 4) * CE;
            int j0 = (tid & 15) << 2;
            unsigned long long acc[CE][2] = {};
            #pragma unroll 4
            for (int cc = 0; cc < 64; cc++) {
                const unsigned long long* bp = (const unsigned long long*)&sW2[cc * 64 + j0];
                unsigned long long b0 = bp[0], b1 = bp[1];
                #pragma unroll
                for (int i = 0; i < CE; i++) {
                    unsigned long long a2 = pack2(sHa[(e0 + i) * 64 + cc]);
                    fma2(acc[i][0], a2, b0);
                    fma2(acc[i][1], a2, b1);
                }
            }
            #pragma unroll
            for (int i = 0; i < CE; i++) {
                float2 p0 = unpack2(acc[i][0]);
                float2 p1 = unpack2(acc[i][1]);
                float* dst = &sHb[(e0 + i) * 64 + j0];
                dst[0] = silu_f(p0.x);
                dst[1] = silu_f(p0.y);
                dst[2] = silu_f(p1.x);
                dst[3] = silu_f(p1.y);
            }
        }
        __syncthreads();

        // Phase D+E fused: TPW = H2 @ W3 then tensor product + red scatter.
        // Thread tile: DE edges x 2 channels x NB paths (acc in regs, no spill
        // at the 512-thread / 128-reg cap).
        {
            constexpr int DE = FIRST ? 8 : 4;     // edges per thread (warp-uniform)
            int eb = (tid >> 5) * DE;
            int cb = (tid & 31) << 1;
            unsigned long long acc[DE][NB];
            #pragma unroll
            for (int ii = 0; ii < DE; ii++)
                #pragma unroll
                for (int p = 0; p < NB; p++) acc[ii][p] = 0ull;

            #pragma unroll 2
            for (int cc = 0; cc < 64; cc++) {
                const float* wrow = &sW3[cc * 320 + cb];
                unsigned long long b[NB];
                #pragma unroll
                for (int p = 0; p < NB; p++)
                    b[p] = *(const unsigned long long*)(wrow + 64 * p);
                #pragma unroll
                for (int ii = 0; ii < DE; ii++) {
                    unsigned long long a2 = pack2(sHb[(eb + ii) * 64 + cc]);
                    #pragma unroll
                    for (int p = 0; p < NB; p++) fma2(acc[ii][p], a2, b[p]);
                }
            }

            // epilogue: per edge, per channel-pair, build messages + scatter
            #pragma unroll 1
            for (int ii = 0; ii < DE; ii++) {
                int el = eb + ii;
                int r = sRecv[el];
                if (r < 0) continue;
                int s = sSend[el];
                float4 Yv = sY[el];
                const float4* xp = &d_x[(size_t)s * CCH + cb];
                float4 xs0 = xp[0];
                float4 xs1 = xp[1];
                float2 t0 = unpack2(acc[ii][0]);
                float2 t1 = unpack2(acc[ii][1]);
                float2 t2 = make_float2(0, 0), t3 = make_float2(0, 0), t4 = make_float2(0, 0);
                if (!FIRST) {
                    t2 = unpack2(acc[ii][2]);
                    t3 = unpack2(acc[ii][3]);
                    t4 = unpack2(acc[ii][4]);
                }
                float* dst = (float*)&d_M[(size_t)r * CCH + cb];
                emit_msg<FIRST>(dst,     xs0, Yv, t0.x, t1.x, t2.x, t3.x, t4.x);
                emit_msg<FIRST>(dst + 4, xs1, Yv, t0.y, t1.y, t2.y, t3.y, t4.y);
            }
        }
    }
}

// ---------------------------------------------------------------------------
// Fused post(l0)+up(l1) / final post
// ---------------------------------------------------------------------------
#define SMP_LW0 0
#define SMP_LW1 4096
#define SMP_PL0 8192
#define SMP_PL1 12288
#define SMP_PW0 16384
#define SMP_PW1 17152
#define SMP_A   17664
#define SMP_B   18688
#define SMP_TOT 19712   // floats

template<bool FINAL>
__global__ void __launch_bounds__(256) k_post(
    const int* __restrict__ species,
    const float* __restrict__ LW0g, const float* __restrict__ LW1g,
    const float* __restrict__ PW0g, const float* __restrict__ PW1g,
    const float* __restrict__ PL0g, const float* __restrict__ PL1g,
    float4* __restrict__ out, int N_)
{
    extern __shared__ float sm[];
    float* sLW0 = sm + SMP_LW0;
    float* sLW1 = sm + SMP_LW1;
    float* sPL0 = sm + SMP_PL0;
    float* sPL1 = sm + SMP_PL1;
    float* sPW0 = sm + SMP_PW0;
    float* sPW1 = sm + SMP_PW1;
    float4* sA = (float4*)(sm + SMP_A);
    float4* sB = (float4*)(sm + SMP_B);
    int tid = threadIdx.x;
    const float INV_SQRT3 = 0.5773502691896258f;
    for (int i = tid; i < 4096; i += 256) {
        sLW0[i] = LW0g[i];
        sLW1[i] = LW1g[i];
        sPL0[i] = PL0g[i];
        sPL1[i] = PL1g[i];
    }
    for (int i = tid; i < 768; i += 256) sPW0[i] = PW0g[i];
    for (int i = tid; i < 512; i += 256) sPW1[i] = PW1g[i];
    __syncthreads();

    int base = blockIdx.x * 64;
    int c = tid & 63, sub = tid >> 6;
    for (int g = 0; g < 16; g++) {
        int n = base + g * 4 + sub;
        bool act = n < N_;
        if (act) {
            float4 mv = d_M[(size_t)n * CCH + c];
            mv.x *= 0.0625f; mv.y *= 0.0625f; mv.z *= 0.0625f; mv.w *= 0.0625f;
            sA[sub * CCH + c] = mv;
        }
        __syncthreads();
        if (act) {
            float h0 = 0, h1x = 0, h1y = 0, h1z = 0;
            const float4* ar = &sA[sub * CCH];
            #pragma unroll 8
            for (int cc = 0; cc < 64; cc++) {
                float4 a = ar[cc];
                float w0 = sLW0[cc * 64 + c];
                float w1 = sLW1[cc * 64 + c];
                h0 += a.x * w0;
                h1x += a.y * w1;
                h1y += a.z * w1;
                h1z += a.w * w1;
            }
            int sp = species[n];
            float nrm = (h1x * h1x + h1y * h1y + h1z * h1z) * INV_SQRT3;
            const float* p0 = &sPW0[sp * 192 + c];
            float b0 = p0[0] * h0 + p0[64] * h0 * h0 + p0[128] * nrm;
            const float* p1 = &sPW1[sp * 128 + c];
            float q = p1[0] + p1[64] * h0;
            sB[sub * CCH + c] = make_float4(b0, q * h1x, q * h1y, q * h1z);
        }
        __syncthreads();
        if (act) {
            float o0 = 0, o1 = 0, o2 = 0, o3 = 0;
            const float4* br = &sB[sub * CCH];
            #pragma unroll 8
            for (int cc = 0; cc < 64; cc++) {
                float4 b = br[cc];
                float w0 = sPL0[cc * 64 + c];
                float w1 = sPL1[cc * 64 + c];
                o0 += b.x * w0;
                o1 += b.y * w1;
                o2 += b.z * w1;
                o3 += b.w * w1;
            }
            if (FINAL) {
                out[(size_t)n * CCH + c] = make_float4(o0, o1, o2, o3);
            } else {
                d_x[(size_t)n * CCH + c] = make_float4(o0, o1, o2, o3);
                d_M[(size_t)n * CCH + c] = make_float4(0, 0, 0, 0);
            }
        }
        __syncthreads();
    }
}

// ---------------------------------------------------------------------------
extern "C" void kernel_launch(void* const* d_in, const int* in_sizes, int n_in,
                              void* d_out, int out_size) {
    const float* positions    = (const float*)d_in[0];
    const int*   species      = (const int*)d_in[1];
    const int*   edge_index   = (const int*)d_in[2];
    const float* node_embed_W = (const float*)d_in[3];
    const float* lin_up_W0    = (const float*)d_in[4];
    const float* lin_up_W1    = (const float*)d_in[5];
    const float* mlp_W1       = (const float*)d_in[6];
    const float* mlp_W2       = (const float*)d_in[7];
    const float* mlp_W3       = (const float*)d_in[8];
    const float* lin_W0       = (const float*)d_in[9];
    const float* lin_W1       = (const float*)d_in[10];
    const float* prod_W0      = (const float*)d_in[11];
    const float* prod_W1      = (const float*)d_in[12];
    const float* prod_lin_W0  = (const float*)d_in[13];
    const float* prod_lin_W1  = (const float*)d_in[14];

    int N_ = in_sizes[0] / 3;
    int E_ = in_sizes[2] / 2;

    size_t smemE = (size_t)SME_TOT * 4;
    size_t smemP = (size_t)SMP_TOT * 4;
    cudaFuncSetAttribute(k_edge<true>,  cudaFuncAttributeMaxDynamicSharedMemorySize, (int)smemE);
    cudaFuncSetAttribute(k_edge<false>, cudaFuncAttributeMaxDynamicSharedMemorySize, (int)smemE);
    cudaFuncSetAttribute(k_post<true>,  cudaFuncAttributeMaxDynamicSharedMemorySize, (int)smemP);
    cudaFuncSetAttribute(k_post<false>, cudaFuncAttributeMaxDynamicSharedMemorySize, (int)smemP);

    k_geom<<<(E_ + 255) / 256, 256>>>(positions, edge_index, E_);
    k_prepw<<<1, 256>>>(node_embed_W, lin_up_W0,
                        prod_lin_W0, lin_up_W0 + 4096,
                        prod_lin_W1, lin_up_W1 + 4096);
    k_seed<<<(N_ * CCH + 255) / 256, 256>>>(species, N_);

    void* p0;
    void* p1;
    cudaGetSymbolAddress(&p0, d_W0c);
    cudaGetSymbolAddress(&p1, d_W1c);
    const float* W0c_sym = (const float*)p0;
    const float* W1c_sym = (const float*)p1;

    // layer 0
    k_edge<true><<<EGRID, ETHREADS, smemE>>>(edge_index, mlp_W1, mlp_W2, mlp_W3, E_);
    k_post<false><<<(N_ + 63) / 64, 256, smemP>>>(
        species, lin_W0, lin_W1, prod_W0, prod_W1,
        W0c_sym, W1c_sym, nullptr, N_);

    // layer 1
    k_edge<false><<<EGRID, ETHREADS, smemE>>>(
        edge_index, mlp_W1 + 512, mlp_W2 + 4096, mlp_W3 + 20480, E_);
    k_post<true><<<(N_ + 63) / 64, 256, smemP>>>(
        species, lin_W0 + 4096, lin_W1 + 4096,
        prod_W0 + 768, prod_W1 + 512,
        prod_lin_W0 + 4096, prod_lin_W1 + 4096,
        (float4*)d_out, N_);
}